// round 2
// baseline (speedup 1.0000x reference)
#include <cuda_runtime.h>
#include <math.h>

#define NN 50000
#define EE 800000
#define INF 128
#define HH 64
#define KK 5
#define EPS 0.001f

// ---------------- scratch (static device globals; no allocations) ----------------
__device__ float g_h[NN * HH];        // node hidden state
__device__ float g_hsd[NN * 2 * HH];  // [hs | hd] per node
__device__ float g_hw[NN * HH];       // h * w_relation
__device__ int   g_indeg[NN];
__device__ int   g_off[NN + 1];
__device__ int   g_cursor[NN];
__device__ int   g_ssrc[EE];          // src sorted by dst (CSR payload)

// ---------------- helpers ----------------
__device__ __forceinline__ float sigm(float x) { return 1.0f / (1.0f + expf(-x)); }
__device__ __forceinline__ float softplus(float x) {
    return fmaxf(x, 0.0f) + log1pf(expf(-fabsf(x)));
}

// ---------------- embed: h = node_feat @ emb_w + emb_b ----------------
// 256 threads = 4 groups x 64; W (128x64) staged in shared once per block.
__global__ void k_embed(const float* __restrict__ x, const float* __restrict__ W,
                        const float* __restrict__ b) {
    __shared__ float sW[INF * HH];
    __shared__ float sx[4][INF];
    __shared__ float sb[HH];
    int t = threadIdx.x;
    for (int i = t; i < INF * HH; i += 256) sW[i] = W[i];
    if (t < HH) sb[t] = b[t];
    __syncthreads();
    int g = t >> 6, j = t & 63;
    for (int row0 = blockIdx.x * 4; row0 < NN; row0 += gridDim.x * 4) {
        int row = row0 + g;
        if (row < NN) {
            sx[g][j] = x[row * INF + j];
            sx[g][j + 64] = x[row * INF + j + 64];
        }
        __syncthreads();
        if (row < NN) {
            float acc = sb[j];
            #pragma unroll
            for (int k = 0; k < INF; k++) acc += sx[g][k] * sW[k * HH + j];
            g_h[row * HH + j] = acc;
        }
        __syncthreads();
    }
}

// ---------------- per-layer linear: hsd[n] = [ h[n]@w_s | h[n]@w_d ] ----------------
// conv_w layer slice is [2H, H] row-major. 256 threads = 2 groups x 128.
__global__ void k_lin(const float* __restrict__ W /* layer slice [128][64] */) {
    __shared__ float sW[2 * HH * HH];
    __shared__ float sx[2][HH];
    int t = threadIdx.x;
    for (int i = t; i < 2 * HH * HH; i += 256) sW[i] = W[i];
    __syncthreads();
    int g = t >> 7, tt = t & 127;
    for (int row0 = blockIdx.x * 2; row0 < NN; row0 += gridDim.x * 2) {
        int row = row0 + g;
        if (row < NN && tt < HH) sx[g][tt] = g_h[row * HH + tt];
        __syncthreads();
        if (row < NN) {
            int base = (tt >= HH) ? HH : 0;
            int j = tt & 63;
            float acc = 0.0f;
            #pragma unroll
            for (int k = 0; k < HH; k++) acc += sx[g][k] * sW[(base + k) * HH + j];
            g_hsd[row * 2 * HH + tt] = acc;
        }
        __syncthreads();
    }
}

// ---------------- CSR build ----------------
__global__ void k_zero() {
    int i = blockIdx.x * blockDim.x + threadIdx.x;
    if (i < NN) { g_indeg[i] = 0; g_cursor[i] = 0; }
}
__global__ void k_count(const int* __restrict__ dst) {
    int e = blockIdx.x * blockDim.x + threadIdx.x;
    if (e < EE) atomicAdd(&g_indeg[dst[e]], 1);
}
__global__ void k_scan() {  // single block, 1024 threads
    __shared__ int ssum[1024];
    int t = threadIdx.x;
    const int CH = (NN + 1023) / 1024;
    int base = t * CH;
    int s = 0;
    for (int i = 0; i < CH; i++) {
        int idx = base + i;
        if (idx < NN) s += g_indeg[idx];
    }
    ssum[t] = s;
    __syncthreads();
    for (int off = 1; off < 1024; off <<= 1) {
        int v = (t >= off) ? ssum[t - off] : 0;
        __syncthreads();
        ssum[t] += v;
        __syncthreads();
    }
    int run = ssum[t] - s;  // exclusive prefix
    for (int i = 0; i < CH; i++) {
        int idx = base + i;
        if (idx < NN) { g_off[idx] = run; run += g_indeg[idx]; }
    }
    if (t == 1023) g_off[NN] = run;
}
__global__ void k_scatter(const int* __restrict__ src, const int* __restrict__ dst) {
    int e = blockIdx.x * blockDim.x + threadIdx.x;
    if (e < EE) {
        int d = dst[e];
        int p = atomicAdd(&g_cursor[d], 1);
        g_ssrc[g_off[d] + p] = src[e];
    }
}

// ---------------- gather + full node update (one warp per node) ----------------
__global__ void k_gather_update(const float* __restrict__ cb,
                                const float* __restrict__ gamma,
                                const float* __restrict__ beta,
                                const float* __restrict__ mean,
                                const float* __restrict__ var) {
    int warp = (blockIdx.x * blockDim.x + threadIdx.x) >> 5;
    int lane = threadIdx.x & 31;
    if (warp >= NN) return;
    int n = warp;
    int s0 = g_off[n], s1 = g_off[n + 1];
    float a0 = 0.0f, a1 = 0.0f;
    for (int i = s0; i < s1; i++) {
        int s = g_ssrc[i];
        float2 v = *(const float2*)&g_hsd[s * 2 * HH + 2 * lane];
        a0 += v.x; a1 += v.y;
    }
    float deg = (float)(s1 - s0);
    float2 hd = *(const float2*)&g_hsd[n * 2 * HH + HH + 2 * lane];
    int j0 = 2 * lane, j1 = 2 * lane + 1;
    float agg0 = a0 + deg * (hd.x + cb[j0]);
    float agg1 = a1 + deg * (hd.y + cb[j1]);
    float2 hold = *(const float2*)&g_h[n * HH + 2 * lane];
    float x0 = sigm(agg0) + softplus(hold.x);
    float x1 = sigm(agg1) + softplus(hold.y);
    x0 = gamma[j0] * (x0 - mean[j0]) * rsqrtf(var[j0] + EPS) + beta[j0];
    x1 = gamma[j1] * (x1 - mean[j1]) * rsqrtf(var[j1] + EPS) + beta[j1];
    x0 = fmaxf(x0, 0.0f);
    x1 = fmaxf(x1, 0.0f);
    float2 out = make_float2(x0, x1);
    *(float2*)&g_h[n * HH + 2 * lane] = out;
}

// ---------------- hw = h * w_relation ----------------
__global__ void k_hw(const float* __restrict__ wrel) {
    int i = blockIdx.x * blockDim.x + threadIdx.x;
    if (i < NN * HH) g_hw[i] = g_h[i] * wrel[i & 63];
}

// ---------------- positive scores: 16 threads per edge ----------------
__global__ void k_pos(const int* __restrict__ src, const int* __restrict__ dst,
                      float* __restrict__ out) {
    int gid = blockIdx.x * blockDim.x + threadIdx.x;
    int e = gid >> 4;
    int c = gid & 15;
    if (e >= EE) return;
    int s = src[e], d = dst[e];
    float4 a = *(const float4*)&g_hw[s * HH + 4 * c];
    float4 b = *(const float4*)&g_h[d * HH + 4 * c];
    float p = a.x * b.x + a.y * b.y + a.z * b.z + a.w * b.w;
    p += __shfl_xor_sync(0xffffffffu, p, 8);
    p += __shfl_xor_sync(0xffffffffu, p, 4);
    p += __shfl_xor_sync(0xffffffffu, p, 2);
    p += __shfl_xor_sync(0xffffffffu, p, 1);
    if (c == 0) out[e] = p;
}

// ---------------- negative scores: 16 threads per edge, loop K negs ----------------
__global__ void k_neg(const int* __restrict__ src, const int* __restrict__ neg_dst,
                      float* __restrict__ out) {
    int gid = blockIdx.x * blockDim.x + threadIdx.x;
    int e = gid >> 4;
    int c = gid & 15;
    if (e >= EE) return;
    int s = src[e];
    float4 a = *(const float4*)&g_hw[s * HH + 4 * c];
    #pragma unroll
    for (int k = 0; k < KK; k++) {
        int nd = neg_dst[e * KK + k];
        float4 b = *(const float4*)&g_h[nd * HH + 4 * c];
        float p = a.x * b.x + a.y * b.y + a.z * b.z + a.w * b.w;
        p += __shfl_xor_sync(0xffffffffu, p, 8);
        p += __shfl_xor_sync(0xffffffffu, p, 4);
        p += __shfl_xor_sync(0xffffffffu, p, 2);
        p += __shfl_xor_sync(0xffffffffu, p, 1);
        if (c == 0) out[e * KK + k] = p;
    }
}

// ---------------- launch ----------------
extern "C" void kernel_launch(void* const* d_in, const int* in_sizes, int n_in,
                              void* d_out, int out_size) {
    const float* node_feat = (const float*)d_in[0];
    const float* emb_w     = (const float*)d_in[1];
    const float* emb_b     = (const float*)d_in[2];
    const float* conv_w    = (const float*)d_in[3];
    const float* conv_b    = (const float*)d_in[4];
    const float* bn_gamma  = (const float*)d_in[5];
    const float* bn_beta   = (const float*)d_in[6];
    const float* bn_mean   = (const float*)d_in[7];
    const float* bn_var    = (const float*)d_in[8];
    const float* w_rel     = (const float*)d_in[9];
    const int*   src       = (const int*)d_in[10];
    const int*   dst       = (const int*)d_in[11];
    const int*   neg_dst   = (const int*)d_in[12];
    float* out = (float*)d_out;

    // CSR build (recomputed every replay; graph is static but cheap)
    k_zero<<<(NN + 255) / 256, 256>>>();
    k_count<<<(EE + 255) / 256, 256>>>(dst);
    k_scan<<<1, 1024>>>();
    k_scatter<<<(EE + 255) / 256, 256>>>(src, dst);

    // embedding
    k_embed<<<592, 256>>>(node_feat, emb_w, emb_b);

    // two conv layers
    for (int i = 0; i < 2; i++) {
        k_lin<<<592, 256>>>(conv_w + (size_t)i * 2 * HH * HH);
        k_gather_update<<<(NN * 32 + 255) / 256, 256>>>(
            conv_b + i * HH, bn_gamma + i * HH, bn_beta + i * HH,
            bn_mean + i * HH, bn_var + i * HH);
    }

    // scoring
    k_hw<<<(NN * HH + 255) / 256, 256>>>(w_rel);
    k_pos<<<(EE * 16 + 255) / 256, 256>>>(src, dst, out);
    k_neg<<<(EE * 16 + 255) / 256, 256>>>(src, neg_dst, out + EE);
}

// round 3
// speedup vs baseline: 1.0207x; 1.0207x over previous
#include <cuda_runtime.h>
#include <math.h>

#define NN 50000
#define EE 800000
#define INF 128
#define HH 64
#define KK 5
#define EPS 0.001f

// ---------------- scratch (static device globals; no allocations) ----------------
__device__ float g_h[NN * HH];        // node hidden state
__device__ float g_hsd[NN * 2 * HH];  // [hs | hd] per node
__device__ float g_hw[NN * HH];       // h * w_relation
__device__ int   g_indeg[NN];
__device__ int   g_off[NN + 1];
__device__ int   g_cursor[NN];
__device__ int   g_ssrc[EE];          // src sorted by dst (CSR payload)

// ---------------- helpers ----------------
__device__ __forceinline__ float sigm(float x) { return 1.0f / (1.0f + expf(-x)); }
__device__ __forceinline__ float softplus(float x) {
    return fmaxf(x, 0.0f) + log1pf(expf(-fabsf(x)));
}

// ---------------- embed: h = node_feat @ emb_w + emb_b ----------------
// Register-blocked: 64 rows x 64 cols per block; thread = 4 rows x 4 cols.
// K=128 staged in two 64-wide chunks. sW 32KB + sx 16KB = 48KB shared.
__global__ void k_embed(const float* __restrict__ x, const float* __restrict__ W,
                        const float* __restrict__ b) {
    __shared__ float sW[INF][HH];   // 32KB
    __shared__ float sx[64][64];    // 16KB (one k-chunk)
    int t = threadIdx.x;
    int tx = t & 15, ty = t >> 4;   // tx: 16 col-groups of 4; ty: 16 row-groups of 4
    const float4* W4 = (const float4*)W;
    float4* sW4 = (float4*)&sW[0][0];
    for (int i = t; i < INF * HH / 4; i += 256) sW4[i] = W4[i];

    int row0 = blockIdx.x * 64;
    float acc[4][4] = {};

    for (int kc = 0; kc < INF; kc += 64) {
        __syncthreads();
        // stage x chunk: 64 rows x 64 floats = 1024 float4
        for (int i = t; i < 1024; i += 256) {
            int r = i >> 4, c = i & 15;
            int row = row0 + r;
            float4 v = make_float4(0.f, 0.f, 0.f, 0.f);
            if (row < NN) v = *(const float4*)&x[row * INF + kc + 4 * c];
            *((float4*)&sx[r][0] + c) = v;
        }
        __syncthreads();
        #pragma unroll 4
        for (int k = 0; k < 64; k++) {
            float4 w = *(const float4*)&sW[kc + k][tx * 4];
            #pragma unroll
            for (int r = 0; r < 4; r++) {
                float xv = sx[ty * 4 + r][k];
                acc[r][0] += xv * w.x; acc[r][1] += xv * w.y;
                acc[r][2] += xv * w.z; acc[r][3] += xv * w.w;
            }
        }
    }
    float4 bb = *(const float4*)&b[tx * 4];
    #pragma unroll
    for (int r = 0; r < 4; r++) {
        int row = row0 + ty * 4 + r;
        if (row < NN) {
            float4 o = make_float4(acc[r][0] + bb.x, acc[r][1] + bb.y,
                                   acc[r][2] + bb.z, acc[r][3] + bb.w);
            *(float4*)&g_h[row * HH + tx * 4] = o;
        }
    }
}

// ---------------- per-layer linear: hsd[n][0:128] = h[n] @ Wc[64x128] ----------------
// Wc[k][j] = (j<64) ? W[k][j] : W[64+k][j-64]  (merged src/dst weights).
// 64 rows x 128 cols per block; thread = 8 rows x 4 cols. sW 32KB + sx 16KB.
__global__ void k_lin(const float* __restrict__ W /* layer slice [128][64] */) {
    __shared__ float sW[HH][2 * HH];  // 32KB, rearranged
    __shared__ float sx[64][HH];      // 16KB
    int t = threadIdx.x;
    int tx = t & 31, ty = t >> 5;     // tx: 32 col-groups of 4; ty: 8 row-groups of 8

    for (int i = t; i < HH * 2 * HH; i += 256) {
        int k = i >> 7, j = i & 127;
        sW[k][j] = (j < HH) ? W[k * HH + j] : W[(HH + k) * HH + (j - HH)];
    }
    int row0 = blockIdx.x * 64;
    for (int i = t; i < 1024; i += 256) {
        int r = i >> 4, c = i & 15;
        int row = row0 + r;
        float4 v = make_float4(0.f, 0.f, 0.f, 0.f);
        if (row < NN) v = *(const float4*)&g_h[row * HH + 4 * c];
        *((float4*)&sx[r][0] + c) = v;
    }
    __syncthreads();

    float acc[8][4] = {};
    #pragma unroll 4
    for (int k = 0; k < HH; k++) {
        float4 w = *(const float4*)&sW[k][tx * 4];
        #pragma unroll
        for (int r = 0; r < 8; r++) {
            float xv = sx[ty * 8 + r][k];
            acc[r][0] += xv * w.x; acc[r][1] += xv * w.y;
            acc[r][2] += xv * w.z; acc[r][3] += xv * w.w;
        }
    }
    #pragma unroll
    for (int r = 0; r < 8; r++) {
        int row = row0 + ty * 8 + r;
        if (row < NN) {
            float4 o = make_float4(acc[r][0], acc[r][1], acc[r][2], acc[r][3]);
            *(float4*)&g_hsd[row * 2 * HH + tx * 4] = o;
        }
    }
}

// ---------------- CSR build ----------------
__global__ void k_zero() {
    int i = blockIdx.x * blockDim.x + threadIdx.x;
    if (i < NN) { g_indeg[i] = 0; g_cursor[i] = 0; }
}
__global__ void k_count(const int* __restrict__ dst) {
    int e = blockIdx.x * blockDim.x + threadIdx.x;
    if (e < EE) atomicAdd(&g_indeg[dst[e]], 1);
}
__global__ void k_scan() {  // single block, 1024 threads
    __shared__ int ssum[1024];
    int t = threadIdx.x;
    const int CH = (NN + 1023) / 1024;
    int base = t * CH;
    int s = 0;
    for (int i = 0; i < CH; i++) {
        int idx = base + i;
        if (idx < NN) s += g_indeg[idx];
    }
    ssum[t] = s;
    __syncthreads();
    for (int off = 1; off < 1024; off <<= 1) {
        int v = (t >= off) ? ssum[t - off] : 0;
        __syncthreads();
        ssum[t] += v;
        __syncthreads();
    }
    int run = ssum[t] - s;  // exclusive prefix
    for (int i = 0; i < CH; i++) {
        int idx = base + i;
        if (idx < NN) { g_off[idx] = run; run += g_indeg[idx]; }
    }
    if (t == 1023) g_off[NN] = run;
}
__global__ void k_scatter(const int* __restrict__ src, const int* __restrict__ dst) {
    int e = blockIdx.x * blockDim.x + threadIdx.x;
    if (e < EE) {
        int d = dst[e];
        int p = atomicAdd(&g_cursor[d], 1);
        g_ssrc[g_off[d] + p] = src[e];
    }
}

// ---------------- gather + full node update (one warp per node) ----------------
// If wrel != nullptr (last layer), also writes g_hw = h * w_relation.
__global__ void k_gather_update(const float* __restrict__ cb,
                                const float* __restrict__ gamma,
                                const float* __restrict__ beta,
                                const float* __restrict__ mean,
                                const float* __restrict__ var,
                                const float* __restrict__ wrel) {
    int warp = (blockIdx.x * blockDim.x + threadIdx.x) >> 5;
    int lane = threadIdx.x & 31;
    if (warp >= NN) return;
    int n = warp;
    int s0 = g_off[n], s1 = g_off[n + 1];
    float a0 = 0.0f, a1 = 0.0f;
    int i = s0;
    for (; i + 1 < s1; i += 2) {
        int sA = g_ssrc[i], sB = g_ssrc[i + 1];
        float2 vA = *(const float2*)&g_hsd[sA * 2 * HH + 2 * lane];
        float2 vB = *(const float2*)&g_hsd[sB * 2 * HH + 2 * lane];
        a0 += vA.x + vB.x; a1 += vA.y + vB.y;
    }
    if (i < s1) {
        int s = g_ssrc[i];
        float2 v = *(const float2*)&g_hsd[s * 2 * HH + 2 * lane];
        a0 += v.x; a1 += v.y;
    }
    float deg = (float)(s1 - s0);
    float2 hd = *(const float2*)&g_hsd[n * 2 * HH + HH + 2 * lane];
    int j0 = 2 * lane, j1 = 2 * lane + 1;
    float agg0 = a0 + deg * (hd.x + cb[j0]);
    float agg1 = a1 + deg * (hd.y + cb[j1]);
    float2 hold = *(const float2*)&g_h[n * HH + 2 * lane];
    float x0 = sigm(agg0) + softplus(hold.x);
    float x1 = sigm(agg1) + softplus(hold.y);
    x0 = gamma[j0] * (x0 - mean[j0]) * rsqrtf(var[j0] + EPS) + beta[j0];
    x1 = gamma[j1] * (x1 - mean[j1]) * rsqrtf(var[j1] + EPS) + beta[j1];
    x0 = fmaxf(x0, 0.0f);
    x1 = fmaxf(x1, 0.0f);
    *(float2*)&g_h[n * HH + 2 * lane] = make_float2(x0, x1);
    if (wrel) {
        *(float2*)&g_hw[n * HH + 2 * lane] = make_float2(x0 * wrel[j0], x1 * wrel[j1]);
    }
}

// ---------------- fused scoring: pos + K negs per edge, 16 threads/edge ----------------
__global__ void k_score(const int* __restrict__ src, const int* __restrict__ dst,
                        const int* __restrict__ neg_dst, float* __restrict__ out) {
    int gid = blockIdx.x * blockDim.x + threadIdx.x;
    int e = gid >> 4;
    int c = gid & 15;
    if (e >= EE) return;
    int s = src[e];
    float4 a = *(const float4*)&g_hw[s * HH + 4 * c];

    // positive
    {
        int d = dst[e];
        float4 b = *(const float4*)&g_h[d * HH + 4 * c];
        float p = a.x * b.x + a.y * b.y + a.z * b.z + a.w * b.w;
        p += __shfl_xor_sync(0xffffffffu, p, 8);
        p += __shfl_xor_sync(0xffffffffu, p, 4);
        p += __shfl_xor_sync(0xffffffffu, p, 2);
        p += __shfl_xor_sync(0xffffffffu, p, 1);
        if (c == 0) out[e] = p;
    }
    // negatives
    #pragma unroll
    for (int k = 0; k < KK; k++) {
        int nd = neg_dst[e * KK + k];
        float4 b = *(const float4*)&g_h[nd * HH + 4 * c];
        float p = a.x * b.x + a.y * b.y + a.z * b.z + a.w * b.w;
        p += __shfl_xor_sync(0xffffffffu, p, 8);
        p += __shfl_xor_sync(0xffffffffu, p, 4);
        p += __shfl_xor_sync(0xffffffffu, p, 2);
        p += __shfl_xor_sync(0xffffffffu, p, 1);
        if (c == 0) out[EE + e * KK + k] = p;
    }
}

// ---------------- launch ----------------
extern "C" void kernel_launch(void* const* d_in, const int* in_sizes, int n_in,
                              void* d_out, int out_size) {
    const float* node_feat = (const float*)d_in[0];
    const float* emb_w     = (const float*)d_in[1];
    const float* emb_b     = (const float*)d_in[2];
    const float* conv_w    = (const float*)d_in[3];
    const float* conv_b    = (const float*)d_in[4];
    const float* bn_gamma  = (const float*)d_in[5];
    const float* bn_beta   = (const float*)d_in[6];
    const float* bn_mean   = (const float*)d_in[7];
    const float* bn_var    = (const float*)d_in[8];
    const float* w_rel     = (const float*)d_in[9];
    const int*   src       = (const int*)d_in[10];
    const int*   dst       = (const int*)d_in[11];
    const int*   neg_dst   = (const int*)d_in[12];
    float* out = (float*)d_out;

    // CSR build
    k_zero<<<(NN + 255) / 256, 256>>>();
    k_count<<<(EE + 255) / 256, 256>>>(dst);
    k_scan<<<1, 1024>>>();
    k_scatter<<<(EE + 255) / 256, 256>>>(src, dst);

    // embedding
    k_embed<<<(NN + 63) / 64, 256>>>(node_feat, emb_w, emb_b);

    // two conv layers (last one also produces hw = h * w_relation)
    for (int i = 0; i < 2; i++) {
        k_lin<<<(NN + 63) / 64, 256>>>(conv_w + (size_t)i * 2 * HH * HH);
        k_gather_update<<<(NN * 32 + 255) / 256, 256>>>(
            conv_b + i * HH, bn_gamma + i * HH, bn_beta + i * HH,
            bn_mean + i * HH, bn_var + i * HH,
            (i == 1) ? w_rel : (const float*)nullptr);
    }

    // fused scoring
    k_score<<<(EE * 16 + 255) / 256, 256>>>(src, dst, neg_dst, out);
}

// round 4
// speedup vs baseline: 1.9552x; 1.9154x over previous
#include <cuda_runtime.h>
#include <cuda_fp16.h>
#include <math.h>

#define NN 50000
#define EE 800000
#define INF 128
#define HH 64
#define KK 5
#define EPS 0.001f

// ---------------- scratch (static device globals; no allocations) ----------------
__device__ float  g_h[NN * HH];        // node hidden state (fp32, inter-layer)
__device__ float  g_hsd[NN * 2 * HH];  // [hs | hd] per node
__device__ __half g_h16[NN * HH];      // final h, fp16 (scoring)
__device__ __half g_hw16[NN * HH];     // final h * w_relation, fp16 (scoring)
__device__ int    g_indeg[NN];
__device__ int    g_off[NN + 1];
__device__ int    g_cursor[NN];
__device__ int    g_ssrc[EE];          // src sorted by dst (CSR payload)

// ---------------- helpers ----------------
__device__ __forceinline__ float sigm(float x) { return 1.0f / (1.0f + expf(-x)); }
__device__ __forceinline__ float softplus(float x) {
    return fmaxf(x, 0.0f) + log1pf(expf(-fabsf(x)));
}

// 8 halves dot 8 halves, fp32 accumulate
__device__ __forceinline__ float dot8h(uint4 ua, uint4 ub) {
    const __half2* a = (const __half2*)&ua;
    const __half2* b = (const __half2*)&ub;
    float acc = 0.0f;
    #pragma unroll
    for (int i = 0; i < 4; i++) {
        float2 fa = __half22float2(a[i]);
        float2 fb = __half22float2(b[i]);
        acc += fa.x * fb.x + fa.y * fb.y;
    }
    return acc;
}

// ---------------- embed: h = node_feat @ emb_w + emb_b ----------------
__global__ void k_embed(const float* __restrict__ x, const float* __restrict__ W,
                        const float* __restrict__ b) {
    __shared__ float sW[INF][HH];   // 32KB
    __shared__ float sx[64][64];    // 16KB (one k-chunk)
    int t = threadIdx.x;
    int tx = t & 15, ty = t >> 4;
    const float4* W4 = (const float4*)W;
    float4* sW4 = (float4*)&sW[0][0];
    for (int i = t; i < INF * HH / 4; i += 256) sW4[i] = W4[i];

    int row0 = blockIdx.x * 64;
    float acc[4][4] = {};

    for (int kc = 0; kc < INF; kc += 64) {
        __syncthreads();
        for (int i = t; i < 1024; i += 256) {
            int r = i >> 4, c = i & 15;
            int row = row0 + r;
            float4 v = make_float4(0.f, 0.f, 0.f, 0.f);
            if (row < NN) v = *(const float4*)&x[row * INF + kc + 4 * c];
            *((float4*)&sx[r][0] + c) = v;
        }
        __syncthreads();
        #pragma unroll 4
        for (int k = 0; k < 64; k++) {
            float4 w = *(const float4*)&sW[kc + k][tx * 4];
            #pragma unroll
            for (int r = 0; r < 4; r++) {
                float xv = sx[ty * 4 + r][k];
                acc[r][0] += xv * w.x; acc[r][1] += xv * w.y;
                acc[r][2] += xv * w.z; acc[r][3] += xv * w.w;
            }
        }
    }
    float4 bb = *(const float4*)&b[tx * 4];
    #pragma unroll
    for (int r = 0; r < 4; r++) {
        int row = row0 + ty * 4 + r;
        if (row < NN) {
            float4 o = make_float4(acc[r][0] + bb.x, acc[r][1] + bb.y,
                                   acc[r][2] + bb.z, acc[r][3] + bb.w);
            *(float4*)&g_h[row * HH + tx * 4] = o;
        }
    }
}

// ---------------- per-layer linear: hsd[n][0:128] = h[n] @ Wc[64x128] ----------------
__global__ void k_lin(const float* __restrict__ W /* layer slice [128][64] */) {
    __shared__ float sW[HH][2 * HH];  // 32KB
    __shared__ float sx[64][HH];      // 16KB
    int t = threadIdx.x;
    int tx = t & 31, ty = t >> 5;

    for (int i = t; i < HH * 2 * HH; i += 256) {
        int k = i >> 7, j = i & 127;
        sW[k][j] = (j < HH) ? W[k * HH + j] : W[(HH + k) * HH + (j - HH)];
    }
    int row0 = blockIdx.x * 64;
    for (int i = t; i < 1024; i += 256) {
        int r = i >> 4, c = i & 15;
        int row = row0 + r;
        float4 v = make_float4(0.f, 0.f, 0.f, 0.f);
        if (row < NN) v = *(const float4*)&g_h[row * HH + 4 * c];
        *((float4*)&sx[r][0] + c) = v;
    }
    __syncthreads();

    float acc[8][4] = {};
    #pragma unroll 4
    for (int k = 0; k < HH; k++) {
        float4 w = *(const float4*)&sW[k][tx * 4];
        #pragma unroll
        for (int r = 0; r < 8; r++) {
            float xv = sx[ty * 8 + r][k];
            acc[r][0] += xv * w.x; acc[r][1] += xv * w.y;
            acc[r][2] += xv * w.z; acc[r][3] += xv * w.w;
        }
    }
    #pragma unroll
    for (int r = 0; r < 8; r++) {
        int row = row0 + ty * 8 + r;
        if (row < NN) {
            float4 o = make_float4(acc[r][0], acc[r][1], acc[r][2], acc[r][3]);
            *(float4*)&g_hsd[row * 2 * HH + tx * 4] = o;
        }
    }
}

// ---------------- CSR build ----------------
__global__ void k_zero() {
    int i = blockIdx.x * blockDim.x + threadIdx.x;
    if (i < NN) { g_indeg[i] = 0; g_cursor[i] = 0; }
}
__global__ void k_count(const int* __restrict__ dst) {
    int e = blockIdx.x * blockDim.x + threadIdx.x;
    if (e < EE) atomicAdd(&g_indeg[dst[e]], 1);
}
__global__ void k_scan() {  // single block, 1024 threads
    __shared__ int ssum[1024];
    int t = threadIdx.x;
    const int CH = (NN + 1023) / 1024;
    int base = t * CH;
    int s = 0;
    for (int i = 0; i < CH; i++) {
        int idx = base + i;
        if (idx < NN) s += g_indeg[idx];
    }
    ssum[t] = s;
    __syncthreads();
    for (int off = 1; off < 1024; off <<= 1) {
        int v = (t >= off) ? ssum[t - off] : 0;
        __syncthreads();
        ssum[t] += v;
        __syncthreads();
    }
    int run = ssum[t] - s;  // exclusive prefix
    for (int i = 0; i < CH; i++) {
        int idx = base + i;
        if (idx < NN) { g_off[idx] = run; run += g_indeg[idx]; }
    }
    if (t == 1023) g_off[NN] = run;
}
__global__ void k_scatter(const int* __restrict__ src, const int* __restrict__ dst) {
    int e = blockIdx.x * blockDim.x + threadIdx.x;
    if (e < EE) {
        int d = dst[e];
        int p = atomicAdd(&g_cursor[d], 1);
        g_ssrc[g_off[d] + p] = src[e];
    }
}

// ---------------- gather + full node update (one warp per node) ----------------
// last==0: writes fp32 g_h.  last==1: writes fp16 g_h16 and g_hw16 only.
__global__ void k_gather_update(const float* __restrict__ cb,
                                const float* __restrict__ gamma,
                                const float* __restrict__ beta,
                                const float* __restrict__ mean,
                                const float* __restrict__ var,
                                const float* __restrict__ wrel,
                                int last) {
    int warp = (blockIdx.x * blockDim.x + threadIdx.x) >> 5;
    int lane = threadIdx.x & 31;
    if (warp >= NN) return;
    int n = warp;
    int s0 = g_off[n], s1 = g_off[n + 1];
    float a0 = 0.0f, a1 = 0.0f;
    int i = s0;
    for (; i + 3 < s1; i += 4) {
        int sA = g_ssrc[i], sB = g_ssrc[i + 1], sC = g_ssrc[i + 2], sD = g_ssrc[i + 3];
        float2 vA = *(const float2*)&g_hsd[sA * 2 * HH + 2 * lane];
        float2 vB = *(const float2*)&g_hsd[sB * 2 * HH + 2 * lane];
        float2 vC = *(const float2*)&g_hsd[sC * 2 * HH + 2 * lane];
        float2 vD = *(const float2*)&g_hsd[sD * 2 * HH + 2 * lane];
        a0 += (vA.x + vB.x) + (vC.x + vD.x);
        a1 += (vA.y + vB.y) + (vC.y + vD.y);
    }
    for (; i < s1; i++) {
        int s = g_ssrc[i];
        float2 v = *(const float2*)&g_hsd[s * 2 * HH + 2 * lane];
        a0 += v.x; a1 += v.y;
    }
    float deg = (float)(s1 - s0);
    float2 hd = *(const float2*)&g_hsd[n * 2 * HH + HH + 2 * lane];
    int j0 = 2 * lane, j1 = 2 * lane + 1;
    float agg0 = a0 + deg * (hd.x + cb[j0]);
    float agg1 = a1 + deg * (hd.y + cb[j1]);
    float2 hold = *(const float2*)&g_h[n * HH + 2 * lane];
    float x0 = sigm(agg0) + softplus(hold.x);
    float x1 = sigm(agg1) + softplus(hold.y);
    x0 = gamma[j0] * (x0 - mean[j0]) * rsqrtf(var[j0] + EPS) + beta[j0];
    x1 = gamma[j1] * (x1 - mean[j1]) * rsqrtf(var[j1] + EPS) + beta[j1];
    x0 = fmaxf(x0, 0.0f);
    x1 = fmaxf(x1, 0.0f);
    if (!last) {
        *(float2*)&g_h[n * HH + 2 * lane] = make_float2(x0, x1);
    } else {
        *(__half2*)&g_h16[n * HH + 2 * lane] = __floats2half2_rn(x0, x1);
        *(__half2*)&g_hw16[n * HH + 2 * lane] =
            __floats2half2_rn(x0 * wrel[j0], x1 * wrel[j1]);
    }
}

// ---------------- fused scoring: pos + K negs per edge, 8 threads/edge, fp16 rows ----
__global__ void k_score(const int* __restrict__ src, const int* __restrict__ dst,
                        const int* __restrict__ neg_dst, float* __restrict__ out) {
    int gid = blockIdx.x * blockDim.x + threadIdx.x;
    int e = gid >> 3;
    int c = gid & 7;
    if (e >= EE) return;
    int s = src[e];
    int d = dst[e];
    // preload all indices for MLP
    int nd[KK];
    #pragma unroll
    for (int k = 0; k < KK; k++) nd[k] = neg_dst[e * KK + k];

    uint4 a = *(const uint4*)&g_hw16[s * HH + 8 * c];
    uint4 bp = *(const uint4*)&g_h16[d * HH + 8 * c];
    uint4 bn[KK];
    #pragma unroll
    for (int k = 0; k < KK; k++)
        bn[k] = *(const uint4*)&g_h16[nd[k] * HH + 8 * c];

    float p = dot8h(a, bp);
    p += __shfl_xor_sync(0xffffffffu, p, 4);
    p += __shfl_xor_sync(0xffffffffu, p, 2);
    p += __shfl_xor_sync(0xffffffffu, p, 1);
    if (c == 0) out[e] = p;

    #pragma unroll
    for (int k = 0; k < KK; k++) {
        float q = dot8h(a, bn[k]);
        q += __shfl_xor_sync(0xffffffffu, q, 4);
        q += __shfl_xor_sync(0xffffffffu, q, 2);
        q += __shfl_xor_sync(0xffffffffu, q, 1);
        if (c == 0) out[EE + e * KK + k] = q;
    }
}

// ---------------- launch ----------------
extern "C" void kernel_launch(void* const* d_in, const int* in_sizes, int n_in,
                              void* d_out, int out_size) {
    const float* node_feat = (const float*)d_in[0];
    const float* emb_w     = (const float*)d_in[1];
    const float* emb_b     = (const float*)d_in[2];
    const float* conv_w    = (const float*)d_in[3];
    const float* conv_b    = (const float*)d_in[4];
    const float* bn_gamma  = (const float*)d_in[5];
    const float* bn_beta   = (const float*)d_in[6];
    const float* bn_mean   = (const float*)d_in[7];
    const float* bn_var    = (const float*)d_in[8];
    const float* w_rel     = (const float*)d_in[9];
    const int*   src       = (const int*)d_in[10];
    const int*   dst       = (const int*)d_in[11];
    const int*   neg_dst   = (const int*)d_in[12];
    float* out = (float*)d_out;

    // CSR build
    k_zero<<<(NN + 255) / 256, 256>>>();
    k_count<<<(EE + 255) / 256, 256>>>(dst);
    k_scan<<<1, 1024>>>();
    k_scatter<<<(EE + 255) / 256, 256>>>(src, dst);

    // embedding
    k_embed<<<(NN + 63) / 64, 256>>>(node_feat, emb_w, emb_b);

    // two conv layers (last one produces fp16 h / hw for scoring)
    for (int i = 0; i < 2; i++) {
        k_lin<<<(NN + 63) / 64, 256>>>(conv_w + (size_t)i * 2 * HH * HH);
        k_gather_update<<<(NN * 32 + 255) / 256, 256>>>(
            conv_b + i * HH, bn_gamma + i * HH, bn_beta + i * HH,
            bn_mean + i * HH, bn_var + i * HH, w_rel, (i == 1) ? 1 : 0);
    }

    // fused scoring (fp16 gathers, fp32 math)
    k_score<<<(EE * 8 + 255) / 256, 256>>>(src, dst, neg_dst, out);
}